// round 8
// baseline (speedup 1.0000x reference)
#include <cuda_runtime.h>
#include <cstdint>

#define HIDDEN 1024
#define HEADS  16
#define DKH    64
#define BB     2
#define NN     2048
#define ROWS   (BB*NN)

__device__ float g_Q[ROWS * HIDDEN];
__device__ float g_K[ROWS * HIDDEN];
__device__ float g_V[ROWS * HIDDEN];
__device__ float g_C[ROWS * HIDDEN];

__device__ __forceinline__ uint32_t f2tf(float x) {
    uint32_t u; asm("cvt.rna.tf32.f32 %0, %1;" : "=r"(u) : "f"(x)); return u;
}
__device__ __forceinline__ uint32_t pk(float a, float b) {
    uint32_t r; asm("cvt.rn.bf16x2.f32 %0, %1, %2;" : "=r"(r) : "f"(b), "f"(a)); return r;
}
__device__ __forceinline__ float blo(uint32_t u) { return __uint_as_float(u << 16); }
__device__ __forceinline__ float bhi(uint32_t u) { return __uint_as_float(u & 0xffff0000u); }
__device__ __forceinline__ void sp(float f0, float f1, uint32_t& h, uint32_t& l) {
    h = pk(f0, f1);
    l = pk(f0 - blo(h), f1 - bhi(h));
}
__device__ __forceinline__ void mma8(float* d, uint32_t a0, uint32_t a1,
    uint32_t a2, uint32_t a3, uint32_t b0, uint32_t b1) {
    asm volatile("mma.sync.aligned.m16n8k8.row.col.f32.tf32.tf32.f32 "
        "{%0,%1,%2,%3},{%4,%5,%6,%7},{%8,%9},{%0,%1,%2,%3};"
        : "+f"(d[0]), "+f"(d[1]), "+f"(d[2]), "+f"(d[3])
        : "r"(a0), "r"(a1), "r"(a2), "r"(a3), "r"(b0), "r"(b1));
}
__device__ __forceinline__ void mma16(float* d, uint32_t a0, uint32_t a1,
    uint32_t a2, uint32_t a3, uint32_t b0, uint32_t b1) {
    asm volatile("mma.sync.aligned.m16n8k16.row.col.f32.bf16.bf16.f32 "
        "{%0,%1,%2,%3},{%4,%5,%6,%7},{%8,%9},{%0,%1,%2,%3};"
        : "+f"(d[0]), "+f"(d[1]), "+f"(d[2]), "+f"(d[3])
        : "r"(a0), "r"(a1), "r"(a2), "r"(a3), "r"(b0), "r"(b1));
}

// ---------------------------------------------------------------------------
// bf16x3 GEMM, double-buffered, interleaved (h,l) smem -> LDS.64 frag loads.
// FIX vs round 7: tile extent is 128(+8 pad) = 136, not 68.
// ---------------------------------------------------------------------------
__global__ void __launch_bounds__(256, 2) gemm_bf3_kernel(
    const float* __restrict__ A, const float* __restrict__ W,
    const float* __restrict__ bias, float* __restrict__ C,
    int M, int N, int K)
{
    __shared__ uint2 Ahl[2][8][136], Whl[2][8][136];   // (hi,lo) per element
    const int tid = threadIdx.x, lane = tid & 31, wid = tid >> 5;
    const int g = lane >> 2, t = lane & 3;
    const int wm = (wid & 3) * 32, wn = (wid >> 2) * 64;
    const float* Ab = A + (size_t)blockIdx.y * 128 * K;
    const float* Wb = W + (size_t)blockIdx.x * 128;

    float acc[2][8][4];
#pragma unroll
    for (int mi = 0; mi < 2; mi++)
#pragma unroll
        for (int n = 0; n < 8; n++)
#pragma unroll
            for (int j = 0; j < 4; j++) acc[mi][n][j] = 0.f;

    const int arow = tid >> 2, ac4 = tid & 3;
    const int kp = tid >> 5, c4 = tid & 31;

    float4 ra0, ra1, rw0, rw1;
#define G_LOAD(k0) do { \
    ra0 = *(const float4*)(Ab + (size_t)arow * K + (k0) + ac4 * 4); \
    ra1 = *(const float4*)(Ab + (size_t)(arow + 64) * K + (k0) + ac4 * 4); \
    rw0 = *(const float4*)(Wb + (size_t)((k0) + 2 * kp) * N + c4 * 4); \
    rw1 = *(const float4*)(Wb + (size_t)((k0) + 2 * kp + 1) * N + c4 * 4); \
} while (0)
#define G_STS(pb) do { \
    uint32_t h_, l_; \
    sp(ra0.x, ra0.y, h_, l_); Ahl[pb][2*ac4][arow]      = make_uint2(h_, l_); \
    sp(ra0.z, ra0.w, h_, l_); Ahl[pb][2*ac4+1][arow]    = make_uint2(h_, l_); \
    sp(ra1.x, ra1.y, h_, l_); Ahl[pb][2*ac4][arow+64]   = make_uint2(h_, l_); \
    sp(ra1.z, ra1.w, h_, l_); Ahl[pb][2*ac4+1][arow+64] = make_uint2(h_, l_); \
    uint4 w0_, w1_; \
    sp(rw0.x, rw1.x, w0_.x, w0_.y); sp(rw0.y, rw1.y, w0_.z, w0_.w); \
    sp(rw0.z, rw1.z, w1_.x, w1_.y); sp(rw0.w, rw1.w, w1_.z, w1_.w); \
    *(uint4*)&Whl[pb][kp][c4 * 4]     = w0_; \
    *(uint4*)&Whl[pb][kp][c4 * 4 + 2] = w1_; \
} while (0)

    G_LOAD(0);
    G_STS(0);
    __syncthreads();
    int p = 0;

    for (int k0 = 0; k0 < K; k0 += 16) {
        if (k0 + 16 < K) G_LOAD(k0 + 16);

        uint2 af[2][4];
#pragma unroll
        for (int mi = 0; mi < 2; mi++) {
            int mb = wm + mi * 16;
            af[mi][0] = Ahl[p][t][mb+g];   af[mi][1] = Ahl[p][t][mb+g+8];
            af[mi][2] = Ahl[p][t+4][mb+g]; af[mi][3] = Ahl[p][t+4][mb+g+8];
        }
#pragma unroll
        for (int n = 0; n < 8; n++) {
            uint2 w0 = Whl[p][t][wn+n*8+g];
            uint2 w1 = Whl[p][t+4][wn+n*8+g];
#pragma unroll
            for (int mi = 0; mi < 2; mi++) {
                mma16(acc[mi][n], af[mi][0].x, af[mi][1].x, af[mi][2].x, af[mi][3].x, w0.x, w1.x);
                mma16(acc[mi][n], af[mi][0].y, af[mi][1].y, af[mi][2].y, af[mi][3].y, w0.x, w1.x);
                mma16(acc[mi][n], af[mi][0].x, af[mi][1].x, af[mi][2].x, af[mi][3].x, w0.y, w1.y);
            }
        }
        if (k0 + 16 < K) G_STS(p ^ 1);
        __syncthreads();
        p ^= 1;
    }

#pragma unroll
    for (int mi = 0; mi < 2; mi++) {
        int row0 = blockIdx.y * 128 + wm + mi * 16 + g;
#pragma unroll
        for (int n = 0; n < 8; n++) {
            int col = blockIdx.x * 128 + wn + n * 8 + 2 * t;
            float2 bv = *(const float2*)(bias + col);
            *(float2*)(C + (size_t)row0 * N + col) =
                make_float2(acc[mi][n][0] + bv.x, acc[mi][n][1] + bv.y);
            *(float2*)(C + (size_t)(row0 + 8) * N + col) =
                make_float2(acc[mi][n][2] + bv.x, acc[mi][n][3] + bv.y);
        }
    }
}

// ---------------------------------------------------------------------------
// Flash: Br=128, Bc=64, 256 thr. Paired layouts for LDS.64 fragment loads:
//  Kp[key][72 u32]:  slot kb*8+2t+s = tf32 K[key][kb*8+t+4s]
//  Vhl[rp][136 u32]: slots (2d, 2d+1) = (bf16h, bf16l), keypair rp, dim d
// Arithmetic identical to round 6 (rel_err must match 1.22e-4).
// ---------------------------------------------------------------------------
__global__ void __launch_bounds__(256) flash_kernel(
    const float* __restrict__ bias, const float* __restrict__ mask,
    float* __restrict__ ctx)
{
    __shared__ uint32_t Kp[64 * 72];     // 18432 B
    __shared__ uint32_t Vhl[32 * 136];   // 17408 B

    const int tid = threadIdx.x, lane = tid & 31, wid = tid >> 5;
    const int g = lane >> 2, t = lane & 3;
    const int wrow = wid * 16;
    const int h = blockIdx.x, q0 = blockIdx.y * 128, b = blockIdx.z;

    const float* Qg = g_Q + ((size_t)b * NN + q0) * HIDDEN + h * DKH;
    const float* Kg = g_K + (size_t)b * NN * HIDDEN + h * DKH;
    const float* Vg = g_V + (size_t)b * NN * HIDDEN + h * DKH;

    const float L2E = 1.44269504088896340736f;
    const float QSC = 0.125f * L2E;

    uint32_t qa[8][4];
#pragma unroll
    for (int kb = 0; kb < 8; kb++) {
        qa[kb][0] = f2tf(__ldg(Qg + (size_t)(wrow+g)  *HIDDEN + kb*8 + t)   * QSC);
        qa[kb][1] = f2tf(__ldg(Qg + (size_t)(wrow+g+8)*HIDDEN + kb*8 + t)   * QSC);
        qa[kb][2] = f2tf(__ldg(Qg + (size_t)(wrow+g)  *HIDDEN + kb*8 + t+4) * QSC);
        qa[kb][3] = f2tf(__ldg(Qg + (size_t)(wrow+g+8)*HIDDEN + kb*8 + t+4) * QSC);
    }

    float Oa[8][4];
#pragma unroll
    for (int n = 0; n < 8; n++)
#pragma unroll
        for (int j = 0; j < 4; j++) Oa[n][j] = 0.f;
    float m0 = -1e30f, m1 = -1e30f, l0 = 0.f, l1 = 0.f;

    const float* biasB = bias + ((size_t)b * NN + q0 + wrow) * NN;
    const float* maskB = mask + ((size_t)b * NN + q0 + wrow) * NN;

    const int kkey = tid >> 3, kkb = tid & 7;    // K loader
    const int vrp  = tid >> 4, vdq = tid & 15;   // V loader

    for (int kt = 0; kt < NN / 64; kt++) {
        const int k0 = kt * 64;
        __syncthreads();

        // ---- K tile: tf32, paired (d, d+4) ----
#pragma unroll
        for (int i = 0; i < 2; i++) {
            int key = kkey + i * 32;
            const float* kr = Kg + (size_t)(k0 + key) * HIDDEN + kkb * 8;
            float4 fa = *(const float4*)kr;
            float4 fb = *(const float4*)(kr + 4);
            uint32_t* d = &Kp[key * 72 + kkb * 8];
            *(uint4*)d       = make_uint4(f2tf(fa.x), f2tf(fb.x), f2tf(fa.y), f2tf(fb.y));
            *(uint4*)(d + 4) = make_uint4(f2tf(fa.z), f2tf(fb.z), f2tf(fa.w), f2tf(fb.w));
        }
        // ---- V tile: bf16 (h,l) interleaved, key-pairs ----
#pragma unroll
        for (int i = 0; i < 2; i++) {
            int rp = vrp + i * 16;
            const float* vr = Vg + (size_t)(k0 + 2 * rp) * HIDDEN + vdq * 4;
            float4 f0 = *(const float4*)vr;
            float4 f1 = *(const float4*)(vr + HIDDEN);
            uint4 u0, u1;
            sp(f0.x, f1.x, u0.x, u0.y); sp(f0.y, f1.y, u0.z, u0.w);
            sp(f0.z, f1.z, u1.x, u1.y); sp(f0.w, f1.w, u1.z, u1.w);
            uint32_t* d = &Vhl[rp * 136 + vdq * 8];
            *(uint4*)d       = u0;
            *(uint4*)(d + 4) = u1;
        }
        __syncthreads();

        // ---- bias+mask pre-summed, log2e folded (16 regs) ----
        const float* b0p = biasB + (size_t)g * NN + k0;
        const float* b1p = biasB + (size_t)(g+8) * NN + k0;
        const float* m0p = maskB + (size_t)g * NN + k0;
        const float* m1p = maskB + (size_t)(g+8) * NN + k0;
        float2 sb0[8], sb1[8];
#pragma unroll
        for (int n = 0; n < 8; n++) {
            float2 u  = __ldg((const float2*)(b0p + n*8 + 2*t));
            float2 um = __ldg((const float2*)(m0p + n*8 + 2*t));
            float2 w  = __ldg((const float2*)(b1p + n*8 + 2*t));
            float2 wm = __ldg((const float2*)(m1p + n*8 + 2*t));
            sb0[n] = make_float2((u.x + um.x) * L2E, (u.y + um.y) * L2E);
            sb1[n] = make_float2((w.x + wm.x) * L2E, (w.y + wm.y) * L2E);
        }

        // ---- S' = (Q*sc*log2e) @ K^T ----
        float sacc[8][4];
#pragma unroll
        for (int n = 0; n < 8; n++)
#pragma unroll
            for (int j = 0; j < 4; j++) sacc[n][j] = 0.f;
#pragma unroll
        for (int kb = 0; kb < 8; kb++)
#pragma unroll
            for (int n = 0; n < 8; n++) {
                uint2 bb = *(const uint2*)&Kp[(n*8+g) * 72 + kb*8 + 2*t];
                mma8(sacc[n], qa[kb][0], qa[kb][1], qa[kb][2], qa[kb][3], bb.x, bb.y);
            }

        // ---- online softmax (exp2 domain) ----
        float mx0 = -1e30f, mx1 = -1e30f;
#pragma unroll
        for (int n = 0; n < 8; n++) {
            sacc[n][0] += sb0[n].x;  sacc[n][1] += sb0[n].y;
            sacc[n][2] += sb1[n].x;  sacc[n][3] += sb1[n].y;
            mx0 = fmaxf(mx0, fmaxf(sacc[n][0], sacc[n][1]));
            mx1 = fmaxf(mx1, fmaxf(sacc[n][2], sacc[n][3]));
        }
        mx0 = fmaxf(mx0, __shfl_xor_sync(~0u, mx0, 1));
        mx0 = fmaxf(mx0, __shfl_xor_sync(~0u, mx0, 2));
        mx1 = fmaxf(mx1, __shfl_xor_sync(~0u, mx1, 1));
        mx1 = fmaxf(mx1, __shfl_xor_sync(~0u, mx1, 2));
        float mn0 = fmaxf(m0, mx0), mn1 = fmaxf(m1, mx1);
        float c0 = exp2f(m0 - mn0), c1 = exp2f(m1 - mn1);
        float rs0 = 0.f, rs1 = 0.f;
#pragma unroll
        for (int n = 0; n < 8; n++) {
            sacc[n][0] = exp2f(sacc[n][0] - mn0);
            sacc[n][1] = exp2f(sacc[n][1] - mn0);
            sacc[n][2] = exp2f(sacc[n][2] - mn1);
            sacc[n][3] = exp2f(sacc[n][3] - mn1);
            rs0 += sacc[n][0] + sacc[n][1];
            rs1 += sacc[n][2] + sacc[n][3];
        }
        rs0 += __shfl_xor_sync(~0u, rs0, 1); rs0 += __shfl_xor_sync(~0u, rs0, 2);
        rs1 += __shfl_xor_sync(~0u, rs1, 1); rs1 += __shfl_xor_sync(~0u, rs1, 2);
        l0 = l0 * c0 + rs0; l1 = l1 * c1 + rs1;
        m0 = mn0; m1 = mn1;
#pragma unroll
        for (int n = 0; n < 8; n++) {
            Oa[n][0] *= c0; Oa[n][1] *= c0;
            Oa[n][2] *= c1; Oa[n][3] *= c1;
        }

        // ---- O += P @ V (bf16x3, P in regs, paired LDS.64 B-frags) ----
#pragma unroll
        for (int kb = 0; kb < 4; kb++) {
            uint32_t a0h, a0l, a1h, a1l, a2h, a2l, a3h, a3l;
            sp(sacc[2*kb][0],   sacc[2*kb][1],   a0h, a0l);
            sp(sacc[2*kb][2],   sacc[2*kb][3],   a1h, a1l);
            sp(sacc[2*kb+1][0], sacc[2*kb+1][1], a2h, a2l);
            sp(sacc[2*kb+1][2], sacc[2*kb+1][3], a3h, a3l);
#pragma unroll
            for (int n = 0; n < 8; n++) {
                uint2 p0 = *(const uint2*)&Vhl[(kb*8+t)   * 136 + (n*8+g) * 2];
                uint2 p1 = *(const uint2*)&Vhl[(kb*8+t+4) * 136 + (n*8+g) * 2];
                mma16(Oa[n], a0h, a1h, a2h, a3h, p0.x, p1.x);
                mma16(Oa[n], a0l, a1l, a2l, a3l, p0.x, p1.x);
                mma16(Oa[n], a0h, a1h, a2h, a3h, p0.y, p1.y);
            }
        }
    }

    float inv0 = 1.f / l0, inv1 = 1.f / l1;
    float* o0 = ctx + ((size_t)b * NN + q0 + wrow + g) * HIDDEN + h * DKH;
    float* o1 = o0 + (size_t)8 * HIDDEN;
#pragma unroll
    for (int n = 0; n < 8; n++) {
        *(float2*)&o0[n*8 + 2*t] = make_float2(Oa[n][0]*inv0, Oa[n][1]*inv0);
        *(float2*)&o1[n*8 + 2*t] = make_float2(Oa[n][2]*inv1, Oa[n][3]*inv1);
    }
}

extern "C" void kernel_launch(void* const* d_in, const int* in_sizes, int n_in,
                              void* d_out, int out_size)
{
    const float* q    = (const float*)d_in[0];
    const float* k    = (const float*)d_in[1];
    const float* v    = (const float*)d_in[2];
    const float* abia = (const float*)d_in[3];
    const float* amask= (const float*)d_in[4];
    const float* Wq   = (const float*)d_in[5];
    const float* bq   = (const float*)d_in[6];
    const float* Wk   = (const float*)d_in[7];
    const float* bk   = (const float*)d_in[8];
    const float* Wv   = (const float*)d_in[9];
    const float* bv   = (const float*)d_in[10];
    const float* Wo   = (const float*)d_in[11];
    const float* bo   = (const float*)d_in[12];
    float* out = (float*)d_out;

    float *Qp, *Kp_, *Vp, *Cp;
    cudaGetSymbolAddress((void**)&Qp, g_Q);
    cudaGetSymbolAddress((void**)&Kp_, g_K);
    cudaGetSymbolAddress((void**)&Vp, g_V);
    cudaGetSymbolAddress((void**)&Cp, g_C);

    dim3 gb(HIDDEN / 128, ROWS / 128);     // (8, 32)
    gemm_bf3_kernel<<<gb, 256>>>(q, Wq, bq, Qp, ROWS, HIDDEN, HIDDEN);
    gemm_bf3_kernel<<<gb, 256>>>(k, Wk, bk, Kp_, ROWS, HIDDEN, HIDDEN);
    gemm_bf3_kernel<<<gb, 256>>>(v, Wv, bv, Vp, ROWS, HIDDEN, HIDDEN);

    dim3 gf(HEADS, NN / 128, BB);          // (16, 16, 2)
    flash_kernel<<<gf, 256>>>(abia, amask, Cp);

    gemm_bf3_kernel<<<gb, 256>>>(Cp, Wo, bo, out, ROWS, HIDDEN, HIDDEN);
}

// round 9
// speedup vs baseline: 1.2675x; 1.2675x over previous
#include <cuda_runtime.h>
#include <cstdint>

#define HIDDEN 1024
#define HEADS  16
#define DKH    64
#define BB     2
#define NN     2048
#define ROWS   (BB*NN)

__device__ float g_Q[ROWS * HIDDEN];
__device__ float g_K[ROWS * HIDDEN];
__device__ float g_V[ROWS * HIDDEN];
__device__ float g_C[ROWS * HIDDEN];

__device__ __forceinline__ uint32_t f2tf(float x) {
    uint32_t u; asm("cvt.rna.tf32.f32 %0, %1;" : "=r"(u) : "f"(x)); return u;
}
__device__ __forceinline__ uint32_t pk(float a, float b) {
    uint32_t r; asm("cvt.rn.bf16x2.f32 %0, %1, %2;" : "=r"(r) : "f"(b), "f"(a)); return r;
}
__device__ __forceinline__ float blo(uint32_t u) { return __uint_as_float(u << 16); }
__device__ __forceinline__ float bhi(uint32_t u) { return __uint_as_float(u & 0xffff0000u); }
__device__ __forceinline__ void sp(float f0, float f1, uint32_t& h, uint32_t& l) {
    h = pk(f0, f1);
    l = pk(f0 - blo(h), f1 - bhi(h));
}
__device__ __forceinline__ void mma8(float* d, uint32_t a0, uint32_t a1,
    uint32_t a2, uint32_t a3, uint32_t b0, uint32_t b1) {
    asm volatile("mma.sync.aligned.m16n8k8.row.col.f32.tf32.tf32.f32 "
        "{%0,%1,%2,%3},{%4,%5,%6,%7},{%8,%9},{%0,%1,%2,%3};"
        : "+f"(d[0]), "+f"(d[1]), "+f"(d[2]), "+f"(d[3])
        : "r"(a0), "r"(a1), "r"(a2), "r"(a3), "r"(b0), "r"(b1));
}
__device__ __forceinline__ void mma16(float* d, uint32_t a0, uint32_t a1,
    uint32_t a2, uint32_t a3, uint32_t b0, uint32_t b1) {
    asm volatile("mma.sync.aligned.m16n8k16.row.col.f32.bf16.bf16.f32 "
        "{%0,%1,%2,%3},{%4,%5,%6,%7},{%8,%9},{%0,%1,%2,%3};"
        : "+f"(d[0]), "+f"(d[1]), "+f"(d[2]), "+f"(d[3])
        : "r"(a0), "r"(a1), "r"(a2), "r"(a3), "r"(b0), "r"(b1));
}

// ---------------------------------------------------------------------------
// bf16x3 GEMM — round-6 version (conflict-free separate h/l arrays,
// double-buffered, 1 sync per k-step, 2 CTA/SM). Measured ~82 us/GEMM.
// ---------------------------------------------------------------------------
__global__ void __launch_bounds__(256, 2) gemm_bf3_kernel(
    const float* __restrict__ A, const float* __restrict__ W,
    const float* __restrict__ bias, float* __restrict__ C,
    int M, int N, int K)
{
    __shared__ uint32_t Ah[2][8][136], Al[2][8][136], Wh[2][8][136], Wl[2][8][136];
    const int tid = threadIdx.x, lane = tid & 31, wid = tid >> 5;
    const int g = lane >> 2, t = lane & 3;
    const int wm = (wid & 3) * 32, wn = (wid >> 2) * 64;
    const float* Ab = A + (size_t)blockIdx.y * 128 * K;
    const float* Wb = W + (size_t)blockIdx.x * 128;

    float acc[2][8][4];
#pragma unroll
    for (int mi = 0; mi < 2; mi++)
#pragma unroll
        for (int n = 0; n < 8; n++)
#pragma unroll
            for (int j = 0; j < 4; j++) acc[mi][n][j] = 0.f;

    const int arow = tid >> 2, ac4 = tid & 3;
    const int kp = tid >> 5, c4 = tid & 31;

    float4 ra0, ra1, rw0, rw1;
#define G_LOAD(k0) do { \
    ra0 = *(const float4*)(Ab + (size_t)arow * K + (k0) + ac4 * 4); \
    ra1 = *(const float4*)(Ab + (size_t)(arow + 64) * K + (k0) + ac4 * 4); \
    rw0 = *(const float4*)(Wb + (size_t)((k0) + 2 * kp) * N + c4 * 4); \
    rw1 = *(const float4*)(Wb + (size_t)((k0) + 2 * kp + 1) * N + c4 * 4); \
} while (0)
#define G_STS(pb) do { \
    uint32_t h_, l_; \
    sp(ra0.x, ra0.y, h_, l_); Ah[pb][2*ac4][arow] = h_;      Al[pb][2*ac4][arow] = l_; \
    sp(ra0.z, ra0.w, h_, l_); Ah[pb][2*ac4+1][arow] = h_;    Al[pb][2*ac4+1][arow] = l_; \
    sp(ra1.x, ra1.y, h_, l_); Ah[pb][2*ac4][arow+64] = h_;   Al[pb][2*ac4][arow+64] = l_; \
    sp(ra1.z, ra1.w, h_, l_); Ah[pb][2*ac4+1][arow+64] = h_; Al[pb][2*ac4+1][arow+64] = l_; \
    uint4 vh_, vl_; \
    sp(rw0.x, rw1.x, vh_.x, vl_.x); sp(rw0.y, rw1.y, vh_.y, vl_.y); \
    sp(rw0.z, rw1.z, vh_.z, vl_.z); sp(rw0.w, rw1.w, vh_.w, vl_.w); \
    *(uint4*)&Wh[pb][kp][c4 * 4] = vh_; \
    *(uint4*)&Wl[pb][kp][c4 * 4] = vl_; \
} while (0)

    G_LOAD(0);
    G_STS(0);
    __syncthreads();
    int p = 0;

    for (int k0 = 0; k0 < K; k0 += 16) {
        if (k0 + 16 < K) G_LOAD(k0 + 16);

        uint32_t af[2][8];
#pragma unroll
        for (int mi = 0; mi < 2; mi++) {
            int mb = wm + mi * 16;
            af[mi][0] = Ah[p][t][mb+g];   af[mi][1] = Ah[p][t][mb+g+8];
            af[mi][2] = Ah[p][t+4][mb+g]; af[mi][3] = Ah[p][t+4][mb+g+8];
            af[mi][4] = Al[p][t][mb+g];   af[mi][5] = Al[p][t][mb+g+8];
            af[mi][6] = Al[p][t+4][mb+g]; af[mi][7] = Al[p][t+4][mb+g+8];
        }
#pragma unroll
        for (int n = 0; n < 8; n++) {
            uint32_t b0h = Wh[p][t][wn+n*8+g], b1h = Wh[p][t+4][wn+n*8+g];
            uint32_t b0l = Wl[p][t][wn+n*8+g], b1l = Wl[p][t+4][wn+n*8+g];
#pragma unroll
            for (int mi = 0; mi < 2; mi++) {
                mma16(acc[mi][n], af[mi][0], af[mi][1], af[mi][2], af[mi][3], b0h, b1h);
                mma16(acc[mi][n], af[mi][4], af[mi][5], af[mi][6], af[mi][7], b0h, b1h);
                mma16(acc[mi][n], af[mi][0], af[mi][1], af[mi][2], af[mi][3], b0l, b1l);
            }
        }
        if (k0 + 16 < K) G_STS(p ^ 1);
        __syncthreads();
        p ^= 1;
    }

#pragma unroll
    for (int mi = 0; mi < 2; mi++) {
        int row0 = blockIdx.y * 128 + wm + mi * 16 + g;
#pragma unroll
        for (int n = 0; n < 8; n++) {
            int col = blockIdx.x * 128 + wn + n * 8 + 2 * t;
            float2 bv = *(const float2*)(bias + col);
            *(float2*)(C + (size_t)row0 * N + col) =
                make_float2(acc[mi][n][0] + bv.x, acc[mi][n][1] + bv.y);
            *(float2*)(C + (size_t)(row0 + 8) * N + col) =
                make_float2(acc[mi][n][2] + bv.x, acc[mi][n][3] + bv.y);
        }
    }
}

// ---------------------------------------------------------------------------
// Flash: Br=128, Bc=64, 256 thr, __launch_bounds__(256,2) -> 16 warps/SM.
// Paired LDS.64 layouts (verified conflict-free). Bias/mask loaded at use.
// Arithmetic identical to rounds 6/8 (rel_err must stay 1.2177e-4).
// ---------------------------------------------------------------------------
__global__ void __launch_bounds__(256, 2) flash_kernel(
    const float* __restrict__ bias, const float* __restrict__ mask,
    float* __restrict__ ctx)
{
    __shared__ uint32_t Kp[64 * 72];     // 18432 B
    __shared__ uint32_t Vhl[32 * 136];   // 17408 B

    const int tid = threadIdx.x, lane = tid & 31, wid = tid >> 5;
    const int g = lane >> 2, t = lane & 3;
    const int wrow = wid * 16;
    const int h = blockIdx.x, q0 = blockIdx.y * 128, b = blockIdx.z;

    const float* Qg = g_Q + ((size_t)b * NN + q0) * HIDDEN + h * DKH;
    const float* Kg = g_K + (size_t)b * NN * HIDDEN + h * DKH;
    const float* Vg = g_V + (size_t)b * NN * HIDDEN + h * DKH;

    const float L2E = 1.44269504088896340736f;
    const float QSC = 0.125f * L2E;

    uint32_t qa[8][4];
#pragma unroll
    for (int kb = 0; kb < 8; kb++) {
        qa[kb][0] = f2tf(__ldg(Qg + (size_t)(wrow+g)  *HIDDEN + kb*8 + t)   * QSC);
        qa[kb][1] = f2tf(__ldg(Qg + (size_t)(wrow+g+8)*HIDDEN + kb*8 + t)   * QSC);
        qa[kb][2] = f2tf(__ldg(Qg + (size_t)(wrow+g)  *HIDDEN + kb*8 + t+4) * QSC);
        qa[kb][3] = f2tf(__ldg(Qg + (size_t)(wrow+g+8)*HIDDEN + kb*8 + t+4) * QSC);
    }

    float Oa[8][4];
#pragma unroll
    for (int n = 0; n < 8; n++)
#pragma unroll
        for (int j = 0; j < 4; j++) Oa[n][j] = 0.f;
    float m0 = -1e30f, m1 = -1e30f, l0 = 0.f, l1 = 0.f;

    const float* biasB = bias + ((size_t)b * NN + q0 + wrow) * NN;
    const float* maskB = mask + ((size_t)b * NN + q0 + wrow) * NN;

    const int kkey = tid >> 3, kkb = tid & 7;
    const int vrp  = tid >> 4, vdq = tid & 15;

    for (int kt = 0; kt < NN / 64; kt++) {
        const int k0 = kt * 64;
        __syncthreads();

        // K tile: tf32 paired (d, d+4)
#pragma unroll
        for (int i = 0; i < 2; i++) {
            int key = kkey + i * 32;
            const float* kr = Kg + (size_t)(k0 + key) * HIDDEN + kkb * 8;
            float4 fa = *(const float4*)kr;
            float4 fb = *(const float4*)(kr + 4);
            uint32_t* d = &Kp[key * 72 + kkb * 8];
            *(uint4*)d       = make_uint4(f2tf(fa.x), f2tf(fb.x), f2tf(fa.y), f2tf(fb.y));
            *(uint4*)(d + 4) = make_uint4(f2tf(fa.z), f2tf(fb.z), f2tf(fa.w), f2tf(fb.w));
        }
        // V tile: bf16 (h,l) interleaved, key-pairs
#pragma unroll
        for (int i = 0; i < 2; i++) {
            int rp = vrp + i * 16;
            const float* vr = Vg + (size_t)(k0 + 2 * rp) * HIDDEN + vdq * 4;
            float4 f0 = *(const float4*)vr;
            float4 f1 = *(const float4*)(vr + HIDDEN);
            uint4 u0, u1;
            sp(f0.x, f1.x, u0.x, u0.y); sp(f0.y, f1.y, u0.z, u0.w);
            sp(f0.z, f1.z, u1.x, u1.y); sp(f0.w, f1.w, u1.z, u1.w);
            uint32_t* d = &Vhl[rp * 136 + vdq * 8];
            *(uint4*)d       = u0;
            *(uint4*)(d + 4) = u1;
        }
        __syncthreads();

        // S' = (Q*sc*log2e) @ K^T
        float sacc[8][4];
#pragma unroll
        for (int n = 0; n < 8; n++)
#pragma unroll
            for (int j = 0; j < 4; j++) sacc[n][j] = 0.f;
#pragma unroll
        for (int kb = 0; kb < 8; kb++)
#pragma unroll
            for (int n = 0; n < 8; n++) {
                uint2 bb = *(const uint2*)&Kp[(n*8+g) * 72 + kb*8 + 2*t];
                mma8(sacc[n], qa[kb][0], qa[kb][1], qa[kb][2], qa[kb][3], bb.x, bb.y);
            }

        // + (bias+mask)*log2e, loaded at use (16 warps cover the latency)
        float mx0 = -1e30f, mx1 = -1e30f;
#pragma unroll
        for (int n = 0; n < 8; n++) {
            float2 u  = __ldg((const float2*)(biasB + (size_t)g    * NN + k0 + n*8 + 2*t));
            float2 um = __ldg((const float2*)(maskB + (size_t)g    * NN + k0 + n*8 + 2*t));
            float2 w  = __ldg((const float2*)(biasB + (size_t)(g+8)* NN + k0 + n*8 + 2*t));
            float2 wm = __ldg((const float2*)(maskB + (size_t)(g+8)* NN + k0 + n*8 + 2*t));
            sacc[n][0] += (u.x + um.x) * L2E;
            sacc[n][1] += (u.y + um.y) * L2E;
            sacc[n][2] += (w.x + wm.x) * L2E;
            sacc[n][3] += (w.y + wm.y) * L2E;
            mx0 = fmaxf(mx0, fmaxf(sacc[n][0], sacc[n][1]));
            mx1 = fmaxf(mx1, fmaxf(sacc[n][2], sacc[n][3]));
        }
        mx0 = fmaxf(mx0, __shfl_xor_sync(~0u, mx0, 1));
        mx0 = fmaxf(mx0, __shfl_xor_sync(~0u, mx0, 2));
        mx1 = fmaxf(mx1, __shfl_xor_sync(~0u, mx1, 1));
        mx1 = fmaxf(mx1, __shfl_xor_sync(~0u, mx1, 2));
        float mn0 = fmaxf(m0, mx0), mn1 = fmaxf(m1, mx1);
        float c0 = exp2f(m0 - mn0), c1 = exp2f(m1 - mn1);
        float rs0 = 0.f, rs1 = 0.f;
#pragma unroll
        for (int n = 0; n < 8; n++) {
            sacc[n][0] = exp2f(sacc[n][0] - mn0);
            sacc[n][1] = exp2f(sacc[n][1] - mn0);
            sacc[n][2] = exp2f(sacc[n][2] - mn1);
            sacc[n][3] = exp2f(sacc[n][3] - mn1);
            rs0 += sacc[n][0] + sacc[n][1];
            rs1 += sacc[n][2] + sacc[n][3];
        }
        rs0 += __shfl_xor_sync(~0u, rs0, 1); rs0 += __shfl_xor_sync(~0u, rs0, 2);
        rs1 += __shfl_xor_sync(~0u, rs1, 1); rs1 += __shfl_xor_sync(~0u, rs1, 2);
        l0 = l0 * c0 + rs0; l1 = l1 * c1 + rs1;
        m0 = mn0; m1 = mn1;
#pragma unroll
        for (int n = 0; n < 8; n++) {
            Oa[n][0] *= c0; Oa[n][1] *= c0;
            Oa[n][2] *= c1; Oa[n][3] *= c1;
        }

        // O += P @ V (bf16x3, P in regs)
#pragma unroll
        for (int kb = 0; kb < 4; kb++) {
            uint32_t a0h, a0l, a1h, a1l, a2h, a2l, a3h, a3l;
            sp(sacc[2*kb][0],   sacc[2*kb][1],   a0h, a0l);
            sp(sacc[2*kb][2],   sacc[2*kb][3],   a1h, a1l);
            sp(sacc[2*kb+1][0], sacc[2*kb+1][1], a2h, a2l);
            sp(sacc[2*kb+1][2], sacc[2*kb+1][3], a3h, a3l);
#pragma unroll
            for (int n = 0; n < 8; n++) {
                uint2 p0 = *(const uint2*)&Vhl[(kb*8+t)   * 136 + (n*8+g) * 2];
                uint2 p1 = *(const uint2*)&Vhl[(kb*8+t+4) * 136 + (n*8+g) * 2];
                mma16(Oa[n], a0h, a1h, a2h, a3h, p0.x, p1.x);
                mma16(Oa[n], a0l, a1l, a2l, a3l, p0.x, p1.x);
                mma16(Oa[n], a0h, a1h, a2h, a3h, p0.y, p1.y);
            }
        }
    }

    float inv0 = 1.f / l0, inv1 = 1.f / l1;
    float* o0 = ctx + ((size_t)b * NN + q0 + wrow + g) * HIDDEN + h * DKH;
    float* o1 = o0 + (size_t)8 * HIDDEN;
#pragma unroll
    for (int n = 0; n < 8; n++) {
        *(float2*)&o0[n*8 + 2*t] = make_float2(Oa[n][0]*inv0, Oa[n][1]*inv0);
        *(float2*)&o1[n*8 + 2*t] = make_float2(Oa[n][2]*inv1, Oa[n][3]*inv1);
    }
}

extern "C" void kernel_launch(void* const* d_in, const int* in_sizes, int n_in,
                              void* d_out, int out_size)
{
    const float* q    = (const float*)d_in[0];
    const float* k    = (const float*)d_in[1];
    const float* v    = (const float*)d_in[2];
    const float* abia = (const float*)d_in[3];
    const float* amask= (const float*)d_in[4];
    const float* Wq   = (const float*)d_in[5];
    const float* bq   = (const float*)d_in[6];
    const float* Wk   = (const float*)d_in[7];
    const float* bk   = (const float*)d_in[8];
    const float* Wv   = (const float*)d_in[9];
    const float* bv   = (const float*)d_in[10];
    const float* Wo   = (const float*)d_in[11];
    const float* bo   = (const float*)d_in[12];
    float* out = (float*)d_out;

    float *Qp, *Kp_, *Vp, *Cp;
    cudaGetSymbolAddress((void**)&Qp, g_Q);
    cudaGetSymbolAddress((void**)&Kp_, g_K);
    cudaGetSymbolAddress((void**)&Vp, g_V);
    cudaGetSymbolAddress((void**)&Cp, g_C);

    dim3 gb(HIDDEN / 128, ROWS / 128);     // (8, 32)
    gemm_bf3_kernel<<<gb, 256>>>(q, Wq, bq, Qp, ROWS, HIDDEN, HIDDEN);
    gemm_bf3_kernel<<<gb, 256>>>(k, Wk, bk, Kp_, ROWS, HIDDEN, HIDDEN);
    gemm_bf3_kernel<<<gb, 256>>>(v, Wv, bv, Vp, ROWS, HIDDEN, HIDDEN);

    dim3 gf(HEADS, NN / 128, BB);          // (16, 16, 2)
    flash_kernel<<<gf, 256>>>(abia, amask, Cp);

    gemm_bf3_kernel<<<gb, 256>>>(Cp, Wo, bo, out, ROWS, HIDDEN, HIDDEN);
}